// round 1
// baseline (speedup 1.0000x reference)
#include <cuda_runtime.h>

// Problem constants
#define BTOT   2048
#define TLEN   512
#define HDIM   64
#define G4     256          // 4*H gates
#define BB     14           // batches per block (compile-time!)
#define XC     128          // x chunk length cached in smem
#define NBLK   148          // grid size: 148*14 = 2072 >= 2048
#define NTH    256          // one thread per gate

// packed f32x2 FMA (sm_100+/sm_103a): acc.lo += w.lo*h.lo ; acc.hi += w.hi*h.hi
__device__ __forceinline__ void fma2(unsigned long long &acc,
                                     unsigned long long w,
                                     unsigned long long h) {
    asm("fma.rn.f32x2 %0, %1, %2, %0;" : "+l"(acc) : "l"(w), "l"(h));
}
__device__ __forceinline__ float2 unpack2(unsigned long long v) {
    float2 r;
    asm("mov.b64 {%0, %1}, %2;" : "=f"(r.x), "=f"(r.y) : "l"(v));
    return r;
}

__device__ __forceinline__ float sigf(float x) {
    // 1/(1+e^-x); __expf = FMUL+MUFU.EX2 (~2ulp), __fdividef = MUFU.RCP+mul
    return __fdividef(1.0f, 1.0f + __expf(-x));
}
__device__ __forceinline__ float tanhfast(float x) {
    // tanh(x) = 1 - 2/(e^{2x}+1); overflow-safe for our pre-activation range
    float e = __expf(2.0f * x);
    return 1.0f - __fdividef(2.0f, e + 1.0f);
}

__global__ void __launch_bounds__(NTH, 1)
lstm_fused_kernel(const float* __restrict__ x,      // [B, T, 1]
                  const float* __restrict__ W_ih,   // [4H, 1]
                  const float* __restrict__ W_hh,   // [4H, H]
                  const float* __restrict__ b_ih,   // [4H]
                  const float* __restrict__ b_hh,   // [4H]
                  const float* __restrict__ fc1_w,  // [16, H]
                  const float* __restrict__ fc1_b,  // [16]
                  const float* __restrict__ fc2_w,  // [1, 16]
                  const float* __restrict__ fc2_b,  // [1]
                  float* __restrict__ out)          // [B, 1]
{
    __shared__ __align__(16) float hsm[BB * HDIM];   // h_{t-1}, read as 128b broadcasts
    __shared__ float gsm[G4 * 17];                   // gate pre-activations, stride 17 (bank-conflict free)
    __shared__ float xs[BB * XC];                    // x slab for current chunk of steps
    __shared__ float zsm[BB * 16];                   // fc1 activations

    const int tid = threadIdx.x;          // == gate index g in [0,256)
    const int b0  = blockIdx.x * BB;      // first global batch of this block

    // Per-thread gate row of W_hh packed into f32x2 pairs (lives in registers).
    unsigned long long w2[HDIM / 2];
    {
        const ulonglong2* wp = reinterpret_cast<const ulonglong2*>(W_hh + tid * HDIM);
        #pragma unroll
        for (int i = 0; i < HDIM / 4; i++) {
            ulonglong2 v = wp[i];
            w2[2 * i]     = v.x;
            w2[2 * i + 1] = v.y;
        }
    }
    const float wih  = W_ih[tid];
    const float bias = b_ih[tid] + b_hh[tid];

    // init h = 0; c lives in the registers of the elementwise-owner thread
    for (int i = tid; i < BB * HDIM; i += NTH) hsm[i] = 0.0f;
    float creg[4] = {0.0f, 0.0f, 0.0f, 0.0f};
    __syncthreads();

    for (int t = 0; t < TLEN; t++) {
        // ---- refill x slab every XC steps (coalesced, masked for tail blocks) ----
        if ((t & (XC - 1)) == 0) {
            for (int m = tid; m < BB * XC; m += NTH) {
                int b  = m >> 7;            // / XC
                int tt = m & (XC - 1);
                int bg = b0 + b;
                xs[m] = (bg < BTOT) ? x[bg * TLEN + t + tt] : 0.0f;
            }
            __syncthreads();
        }
        const int tt = t & (XC - 1);

        // ---- gate phase: thread g computes gate g for all BB batches ----
        // dot(h[b,:], W_hh[g,:]) with packed f32x2 FMAs; two chains for ILP.
        #pragma unroll
        for (int b = 0; b < BB; b += 2) {
            unsigned long long a0 = 0ULL, a1 = 0ULL;
            const ulonglong2* h0 = reinterpret_cast<const ulonglong2*>(hsm + b * HDIM);
            const ulonglong2* h1 = reinterpret_cast<const ulonglong2*>(hsm + (b + 1) * HDIM);
            #pragma unroll
            for (int kk = 0; kk < HDIM / 4; kk++) {
                ulonglong2 p0 = h0[kk];     // LDS.128, broadcast (all lanes same addr)
                ulonglong2 p1 = h1[kk];
                fma2(a0, w2[2 * kk],     p0.x);
                fma2(a1, w2[2 * kk],     p1.x);
                fma2(a0, w2[2 * kk + 1], p0.y);
                fma2(a1, w2[2 * kk + 1], p1.y);
            }
            float2 f0 = unpack2(a0), f1 = unpack2(a1);
            gsm[tid * 17 + b]     = f0.x + f0.y + xs[b * XC + tt]       * wih + bias;
            gsm[tid * 17 + b + 1] = f1.x + f1.y + xs[(b + 1) * XC + tt] * wih + bias;
        }
        __syncthreads();

        // ---- elementwise phase: thread owns units e = tid + 256*q ----
        #pragma unroll
        for (int q = 0; q < 4; q++) {
            int e = tid + q * NTH;
            if (e < BB * HDIM) {
                int b = e >> 6, j = e & 63;
                float gi = sigf(gsm[j * 17 + b]);            // input gate
                float gf = sigf(gsm[(j + 64) * 17 + b]);     // forget gate
                float gc = tanhfast(gsm[(j + 128) * 17 + b]);// cell candidate
                float go = sigf(gsm[(j + 192) * 17 + b]);    // output gate
                float cn = gf * creg[q] + gi * gc;
                creg[q] = cn;
                hsm[b * HDIM + j] = go * tanhfast(cn);
            }
        }
        __syncthreads();
    }

    // ---- MLP head: z = relu(h @ fc1_w^T + fc1_b); out = z @ fc2_w^T + fc2_b ----
    for (int e = tid; e < BB * 16; e += NTH) {
        int b = e >> 4, jj = e & 15;
        float acc = fc1_b[jj];
        const float* wr = fc1_w + jj * HDIM;
        #pragma unroll
        for (int k = 0; k < HDIM; k++) acc += hsm[b * HDIM + k] * wr[k];
        zsm[e] = fmaxf(acc, 0.0f);
    }
    __syncthreads();
    if (tid < BB) {
        int bg = b0 + tid;
        if (bg < BTOT) {
            float acc = fc2_b[0];
            #pragma unroll
            for (int jj = 0; jj < 16; jj++) acc += zsm[tid * 16 + jj] * fc2_w[jj];
            out[bg] = acc;
        }
    }
}

extern "C" void kernel_launch(void* const* d_in, const int* in_sizes, int n_in,
                              void* d_out, int out_size) {
    const float* x     = (const float*)d_in[0];
    const float* W_ih  = (const float*)d_in[1];
    const float* W_hh  = (const float*)d_in[2];
    const float* b_ih  = (const float*)d_in[3];
    const float* b_hh  = (const float*)d_in[4];
    const float* fc1_w = (const float*)d_in[5];
    const float* fc1_b = (const float*)d_in[6];
    const float* fc2_w = (const float*)d_in[7];
    const float* fc2_b = (const float*)d_in[8];
    float* out = (float*)d_out;

    lstm_fused_kernel<<<NBLK, NTH>>>(x, W_ih, W_hh, b_ih, b_hh,
                                     fc1_w, fc1_b, fc2_w, fc2_b, out);
}

// round 3
// speedup vs baseline: 1.1121x; 1.1121x over previous
#include <cuda_runtime.h>

// Problem constants
#define BTOT   2048
#define TLEN   512
#define HDIM   64
#define G4     256          // 4*H gates
#define BB     14           // batches per block
#define HB     7            // batches per group (two groups per block)
#define XC     128          // x chunk length cached in smem
#define NBLK   148          // 148*14 = 2072 >= 2048
#define NTH    512          // 2 groups x 256 threads (one thread per gate)
#define GS     9            // gsm batch stride (odd => conflict-free)

// packed f32x2 FMA (sm_10x): acc.lo += w.lo*h.lo ; acc.hi += w.hi*h.hi
__device__ __forceinline__ void fma2(unsigned long long &acc,
                                     unsigned long long w,
                                     unsigned long long h) {
    asm("fma.rn.f32x2 %0, %1, %2, %0;" : "+l"(acc) : "l"(w), "l"(h));
}
__device__ __forceinline__ float2 unpack2(unsigned long long v) {
    float2 r;
    asm("mov.b64 {%0, %1}, %2;" : "=f"(r.x), "=f"(r.y) : "l"(v));
    return r;
}
__device__ __forceinline__ float sigf(float x) {
    return __fdividef(1.0f, 1.0f + __expf(-x));
}
__device__ __forceinline__ float tanhfast(float x) {
    float e = __expf(2.0f * x);
    return 1.0f - __fdividef(2.0f, e + 1.0f);
}
// named barrier over this group's 256 threads (warp-aligned groups)
__device__ __forceinline__ void gbar(int id) {
    asm volatile("bar.sync %0, %1;" :: "r"(id), "r"(256) : "memory");
}

__global__ void __launch_bounds__(NTH, 1)
lstm_fused_kernel(const float* __restrict__ x,      // [B, T, 1]
                  const float* __restrict__ W_ih,   // [4H, 1]
                  const float* __restrict__ W_hh,   // [4H, H]
                  const float* __restrict__ b_ih,   // [4H]
                  const float* __restrict__ b_hh,   // [4H]
                  const float* __restrict__ fc1_w,  // [16, H]
                  const float* __restrict__ fc1_b,  // [16]
                  const float* __restrict__ fc2_w,  // [1, 16]
                  const float* __restrict__ fc2_b,  // [1]
                  float* __restrict__ out)          // [B, 1]
{
    __shared__ __align__(16) float hsm[2][HB * HDIM];  // h_{t-1} per group
    __shared__ float gsm[2][G4 * GS];                  // gate pre-activations
    __shared__ float xs[2][HB * XC];                   // x slab per group
    __shared__ float zsm[2][HB * 16];                  // fc1 activations

    const int tid = threadIdx.x;
    const int grp = tid >> 8;            // 0 or 1
    const int g   = tid & 255;           // gate row
    const int bar = grp + 1;             // named barrier id (1 or 2)
    const int b0  = blockIdx.x * BB + grp * HB;  // first global batch of group

    // Per-thread gate row of W_hh packed into f32x2 pairs (registers).
    unsigned long long w2[HDIM / 2];
    {
        const ulonglong2* wp = reinterpret_cast<const ulonglong2*>(W_hh + g * HDIM);
        #pragma unroll
        for (int i = 0; i < HDIM / 4; i++) {
            ulonglong2 v = wp[i];
            w2[2 * i]     = v.x;
            w2[2 * i + 1] = v.y;
        }
    }
    const float wih  = W_ih[g];
    const float bias = b_ih[g] + b_hh[g];

    for (int i = g; i < HB * HDIM; i += 256) hsm[grp][i] = 0.0f;
    float c0 = 0.0f, c1 = 0.0f;          // cell state for units g and g+256
    __syncthreads();

    for (int t = 0; t < TLEN; t++) {
        // ---- refill x slab every XC steps (coalesced, masked) ----
        if ((t & (XC - 1)) == 0) {
            for (int m = g; m < HB * XC; m += 256) {
                int b  = m >> 7;
                int tt = m & (XC - 1);
                int bg = b0 + b;
                xs[grp][m] = (bg < BTOT) ? x[bg * TLEN + t + tt] : 0.0f;
            }
            gbar(bar);
        }
        const int tt = t & (XC - 1);
        const float* hp = hsm[grp];

        // ---- gate phase: thread g computes gate g for its 7 batches ----
        #pragma unroll
        for (int bp = 0; bp < 3; bp++) {
            const int b = 2 * bp;
            unsigned long long a0 = 0ULL, a1 = 0ULL;
            const ulonglong2* h0 = reinterpret_cast<const ulonglong2*>(hp + b * HDIM);
            const ulonglong2* h1 = reinterpret_cast<const ulonglong2*>(hp + (b + 1) * HDIM);
            #pragma unroll
            for (int kk = 0; kk < HDIM / 4; kk++) {
                ulonglong2 p0 = h0[kk];     // LDS.128 broadcast
                ulonglong2 p1 = h1[kk];
                fma2(a0, w2[2 * kk],     p0.x);
                fma2(a1, w2[2 * kk],     p1.x);
                fma2(a0, w2[2 * kk + 1], p0.y);
                fma2(a1, w2[2 * kk + 1], p1.y);
            }
            float2 f0 = unpack2(a0), f1 = unpack2(a1);
            gsm[grp][g * GS + b]     = f0.x + f0.y + xs[grp][b * XC + tt]       * wih + bias;
            gsm[grp][g * GS + b + 1] = f1.x + f1.y + xs[grp][(b + 1) * XC + tt] * wih + bias;
        }
        {   // odd 7th batch (b = 6)
            unsigned long long a0 = 0ULL;
            const ulonglong2* h0 = reinterpret_cast<const ulonglong2*>(hp + 6 * HDIM);
            #pragma unroll
            for (int kk = 0; kk < HDIM / 4; kk++) {
                ulonglong2 p0 = h0[kk];
                fma2(a0, w2[2 * kk],     p0.x);
                fma2(a0, w2[2 * kk + 1], p0.y);
            }
            float2 f0 = unpack2(a0);
            gsm[grp][g * GS + 6] = f0.x + f0.y + xs[grp][6 * XC + tt] * wih + bias;
        }
        gbar(bar);

        // ---- elementwise phase: units u = g and u = g+256 (448 units/group) ----
        {
            int b = g >> 6, j = g & 63;
            float gi = sigf(gsm[grp][j * GS + b]);
            float gf = sigf(gsm[grp][(j + 64) * GS + b]);
            float gc = tanhfast(gsm[grp][(j + 128) * GS + b]);
            float go = sigf(gsm[grp][(j + 192) * GS + b]);
            c0 = gf * c0 + gi * gc;
            hsm[grp][b * HDIM + j] = go * tanhfast(c0);
        }
        if (g < 192) {
            int u = g + 256;
            int b = u >> 6, j = u & 63;
            float gi = sigf(gsm[grp][j * GS + b]);
            float gf = sigf(gsm[grp][(j + 64) * GS + b]);
            float gc = tanhfast(gsm[grp][(j + 128) * GS + b]);
            float go = sigf(gsm[grp][(j + 192) * GS + b]);
            c1 = gf * c1 + gi * gc;
            hsm[grp][b * HDIM + j] = go * tanhfast(c1);
        }
        gbar(bar);
    }

    // ---- MLP head (per group): z = relu(h @ fc1^T + b); out = z @ fc2^T + b ----
    if (g < HB * 16) {
        int b = g >> 4, jj = g & 15;
        float acc = fc1_b[jj];
        const float* wr = fc1_w + jj * HDIM;
        #pragma unroll
        for (int k = 0; k < HDIM; k++) acc += hsm[grp][b * HDIM + k] * wr[k];
        zsm[grp][g] = fmaxf(acc, 0.0f);
    }
    gbar(bar);
    if (g < HB) {
        int bg = b0 + g;
        if (bg < BTOT) {
            float acc = fc2_b[0];
            #pragma unroll
            for (int jj = 0; jj < 16; jj++) acc += zsm[grp][g * 16 + jj] * fc2_w[jj];
            out[bg] = acc;
        }
    }
}

extern "C" void kernel_launch(void* const* d_in, const int* in_sizes, int n_in,
                              void* d_out, int out_size) {
    const float* x     = (const float*)d_in[0];
    const float* W_ih  = (const float*)d_in[1];
    const float* W_hh  = (const float*)d_in[2];
    const float* b_ih  = (const float*)d_in[3];
    const float* b_hh  = (const float*)d_in[4];
    const float* fc1_w = (const float*)d_in[5];
    const float* fc1_b = (const float*)d_in[6];
    const float* fc2_w = (const float*)d_in[7];
    const float* fc2_b = (const float*)d_in[8];
    float* out = (float*)d_out;

    lstm_fused_kernel<<<NBLK, NTH>>>(x, W_ih, W_hh, b_ih, b_hh,
                                     fc1_w, fc1_b, fc2_w, fc2_b, out);
}

// round 4
// speedup vs baseline: 1.3561x; 1.2194x over previous
#include <cuda_runtime.h>

// Problem constants
#define BTOT   2048
#define TLEN   512
#define HDIM   64
#define G4     256          // 4*H gates
#define BB     14           // batches per block
#define HB     7            // batches per group (two groups per block)
#define XC     128          // x chunk length cached in smem
#define NBLK   148          // 148*14 = 2072 >= 2048
#define NTH    256          // 2 groups x 128 threads; each thread owns 2 gate rows
#define GS     9            // gsm batch stride (coprime with 32 => conflict-free)

// packed f32x2 FMA (sm_10x): acc.lo += w.lo*h.lo ; acc.hi += w.hi*h.hi
__device__ __forceinline__ void fma2(unsigned long long &acc,
                                     unsigned long long w,
                                     unsigned long long h) {
    asm("fma.rn.f32x2 %0, %1, %2, %0;" : "+l"(acc) : "l"(w), "l"(h));
}
__device__ __forceinline__ float2 unpack2(unsigned long long v) {
    float2 r;
    asm("mov.b64 {%0, %1}, %2;" : "=f"(r.x), "=f"(r.y) : "l"(v));
    return r;
}
__device__ __forceinline__ float sigf(float x) {
    return __fdividef(1.0f, 1.0f + __expf(-x));
}
__device__ __forceinline__ float tanhfast(float x) {
    float e = __expf(2.0f * x);
    return 1.0f - __fdividef(2.0f, e + 1.0f);
}
// named barrier over one group's 128 threads (warp-aligned groups)
__device__ __forceinline__ void gbar(int id) {
    asm volatile("bar.sync %0, %1;" :: "r"(id), "r"(128) : "memory");
}

__global__ void __launch_bounds__(NTH, 1)
lstm_fused_kernel(const float* __restrict__ x,      // [B, T, 1]
                  const float* __restrict__ W_ih,   // [4H, 1]
                  const float* __restrict__ W_hh,   // [4H, H]
                  const float* __restrict__ b_ih,   // [4H]
                  const float* __restrict__ b_hh,   // [4H]
                  const float* __restrict__ fc1_w,  // [16, H]
                  const float* __restrict__ fc1_b,  // [16]
                  const float* __restrict__ fc2_w,  // [1, 16]
                  const float* __restrict__ fc2_b,  // [1]
                  float* __restrict__ out)          // [B, 1]
{
    __shared__ __align__(16) float hsm[2][HB * HDIM];  // h_{t-1} per group
    __shared__ float gsm[2][G4 * GS];                  // gate pre-activations
    __shared__ float xs[2][HB * XC];                   // x slab per group
    __shared__ float zsm[2][HB * 16];                  // fc1 activations

    const int tid  = threadIdx.x;
    const int grp  = tid >> 7;             // 0 or 1
    const int gtid = tid & 127;            // thread-in-group
    const int bar  = grp + 1;              // named barrier id
    const int b0   = blockIdx.x * BB + grp * HB;   // first global batch of group
    const int gA   = gtid;                 // first owned gate row
    const int gB   = gtid + 128;           // second owned gate row

    // Two gate rows of W_hh packed into f32x2 pairs (must stay in registers).
    unsigned long long wA[HDIM / 2], wB[HDIM / 2];
    {
        const ulonglong2* wpA = reinterpret_cast<const ulonglong2*>(W_hh + gA * HDIM);
        const ulonglong2* wpB = reinterpret_cast<const ulonglong2*>(W_hh + gB * HDIM);
        #pragma unroll
        for (int i = 0; i < HDIM / 4; i++) {
            ulonglong2 vA = wpA[i];
            wA[2 * i] = vA.x;  wA[2 * i + 1] = vA.y;
            ulonglong2 vB = wpB[i];
            wB[2 * i] = vB.x;  wB[2 * i + 1] = vB.y;
        }
    }
    const float wihA  = W_ih[gA],           wihB  = W_ih[gB];
    const float biasA = b_ih[gA] + b_hh[gA], biasB = b_ih[gB] + b_hh[gB];

    for (int i = gtid; i < HB * HDIM; i += 128) hsm[grp][i] = 0.0f;
    float creg[4] = {0.0f, 0.0f, 0.0f, 0.0f};  // cell state: units gtid+128q
    gbar(bar);

    for (int t = 0; t < TLEN; t++) {
        // ---- refill x slab every XC steps (coalesced, masked) ----
        if ((t & (XC - 1)) == 0) {
            for (int m = gtid; m < HB * XC; m += 128) {
                int b  = m >> 7;
                int tt = m & (XC - 1);
                int bg = b0 + b;
                xs[grp][m] = (bg < BTOT) ? x[bg * TLEN + t + tt] : 0.0f;
            }
            gbar(bar);
        }
        const int tt = t & (XC - 1);
        const float* hp = hsm[grp];

        // ---- gate phase: 2 gate rows x 7 batches; each h load feeds 4 FFMA2 ----
        #pragma unroll
        for (int b = 0; b < HB; b++) {
            unsigned long long a0 = 0ULL, a1 = 0ULL;
            const ulonglong2* h0 = reinterpret_cast<const ulonglong2*>(hp + b * HDIM);
            #pragma unroll
            for (int kk = 0; kk < HDIM / 4; kk++) {
                ulonglong2 p = h0[kk];      // LDS.128 broadcast
                fma2(a0, wA[2 * kk],     p.x);
                fma2(a1, wB[2 * kk],     p.x);
                fma2(a0, wA[2 * kk + 1], p.y);
                fma2(a1, wB[2 * kk + 1], p.y);
            }
            float2 f0 = unpack2(a0), f1 = unpack2(a1);
            float xv = xs[grp][b * XC + tt];
            gsm[grp][gA * GS + b] = f0.x + f0.y + xv * wihA + biasA;
            gsm[grp][gB * GS + b] = f1.x + f1.y + xv * wihB + biasB;
        }
        gbar(bar);

        // ---- elementwise phase: units u = gtid + 128q (448 units/group) ----
        #pragma unroll
        for (int q = 0; q < 4; q++) {
            int u = gtid + q * 128;
            if (u < HB * HDIM) {
                int b = u >> 6, j = u & 63;
                float gi = sigf(gsm[grp][j * GS + b]);
                float gf = sigf(gsm[grp][(j + 64) * GS + b]);
                float gc = tanhfast(gsm[grp][(j + 128) * GS + b]);
                float go = sigf(gsm[grp][(j + 192) * GS + b]);
                float cn = gf * creg[q] + gi * gc;
                creg[q] = cn;
                hsm[grp][b * HDIM + j] = go * tanhfast(cn);
            }
        }
        gbar(bar);
    }

    // ---- MLP head (per group): z = relu(h @ fc1^T + b); out = z @ fc2^T + b ----
    if (gtid < HB * 16) {
        int b = gtid >> 4, jj = gtid & 15;
        float acc = fc1_b[jj];
        const float* wr = fc1_w + jj * HDIM;
        #pragma unroll
        for (int k = 0; k < HDIM; k++) acc += hsm[grp][b * HDIM + k] * wr[k];
        zsm[grp][gtid] = fmaxf(acc, 0.0f);
    }
    gbar(bar);
    if (gtid < HB) {
        int bg = b0 + gtid;
        if (bg < BTOT) {
            float acc = fc2_b[0];
            #pragma unroll
            for (int jj = 0; jj < 16; jj++) acc += zsm[grp][gtid * 16 + jj] * fc2_w[jj];
            out[bg] = acc;
        }
    }
}

extern "C" void kernel_launch(void* const* d_in, const int* in_sizes, int n_in,
                              void* d_out, int out_size) {
    const float* x     = (const float*)d_in[0];
    const float* W_ih  = (const float*)d_in[1];
    const float* W_hh  = (const float*)d_in[2];
    const float* b_ih  = (const float*)d_in[3];
    const float* b_hh  = (const float*)d_in[4];
    const float* fc1_w = (const float*)d_in[5];
    const float* fc1_b = (const float*)d_in[6];
    const float* fc2_w = (const float*)d_in[7];
    const float* fc2_b = (const float*)d_in[8];
    float* out = (float*)d_out;

    lstm_fused_kernel<<<NBLK, NTH>>>(x, W_ih, W_hh, b_ih, b_hh,
                                     fc1_w, fc1_b, fc2_w, fc2_b, out);
}